// round 5
// baseline (speedup 1.0000x reference)
#include <cuda_runtime.h>
#include <cuda_fp16.h>
#include <cstdint>

// R4 = identical to R3 (cp[8+j] window fix). R3 failed on a transient
// "device busy" harness error before kernel_launch ever ran; resubmitting
// unchanged to actually test the correctness fix.

#define NB 4096
#define NI 256
#define NO 256
#define KF 12
#define KT (NI*KF)        /* 3072 */
#define KC 64             /* fp16 per K-chunk = 128 B row */
#define NCH (KT/KC)       /* 48 chunks */

// ---- static device scratch (no allocations allowed) ----
__device__ __half g_A[(size_t)NB*KT];   // features, 24 MB
__device__ __half g_B[(size_t)NO*KT];   // weights,  1.5 MB

// ---- helpers ----
static __device__ __forceinline__ uint32_t smem_u32(const void* p){
    uint32_t a;
    asm("{ .reg .u64 t; cvta.to.shared.u64 t, %1; cvt.u32.u64 %0, t; }" : "=r"(a) : "l"(p));
    return a;
}
#define SWZ(b) ((b) ^ (((b)>>3)&0x70))

// ---- kernel 1: features F[b, i*12+j] in fp16 ----
// slots j=0..10 map to cp indices 8..18; active at j=t..t+3; slot 11: silu(x)
__global__ void feat_kernel(const float* __restrict__ X){
    __shared__ __half sh[KT];
    int b = blockIdx.x, i = threadIdx.x;
    float x  = X[(size_t)b*NI + i];
    float xs = 8.0f*x;
    int t = (int)floorf(xs);
    t = min(max(t,0),7);
    float u = xs - (float)t;
    float v = 1.0f - u;
    float u2=u*u, u3=u2*u, v3=v*v*v;
    float w0 = v3*(1.0f/6.0f);
    float w1 = (3.0f*u3 - 6.0f*u2 + 4.0f)*(1.0f/6.0f);
    float w2 = (-3.0f*u3 + 3.0f*u2 + 3.0f*u + 1.0f)*(1.0f/6.0f);
    float w3 = u3*(1.0f/6.0f);
    // sigmoid via odd Taylor (max err ~2e-5 on [0,1]) -> pure FFMA, no MUFU
    float z = x*x;
    float sig = 0.5f + x*(0.25f + z*(-(1.0f/48.0f) + z*((1.0f/480.0f) - z*(17.0f/80640.0f))));
    float si = x*sig;
    #pragma unroll
    for (int s=0; s<11; ++s) sh[i*KF+s] = __float2half_rn(0.0f);
    sh[i*KF+t  ] = __float2half_rn(w0);
    sh[i*KF+t+1] = __float2half_rn(w1);
    sh[i*KF+t+2] = __float2half_rn(w2);
    sh[i*KF+t+3] = __float2half_rn(w3);
    sh[i*KF+11] = __float2half_rn(si);
    __syncthreads();
    const uint4* s4 = (const uint4*)sh;
    uint4* d4 = (uint4*)(g_A + (size_t)b*KT);
    for (int k=i; k<KT/8; k+=NI) d4[k] = s4[k];
}

// ---- kernel 2: weights W[o, i*12+j] = sf*cp[8+j] (j<11) / sf (j==11) ----
__global__ void prep_kernel(const float* __restrict__ CP, const float* __restrict__ SF){
    __shared__ __half sh[KT];
    int o = blockIdx.x, i = threadIdx.x;
    float sfv = SF[(size_t)i*NO + o];
    const float* cp = CP + ((size_t)i*NO + o)*19;
    #pragma unroll
    for (int j=0; j<11; ++j) sh[i*KF+j] = __float2half_rn(sfv*cp[8+j]);
    sh[i*KF+11] = __float2half_rn(sfv);
    __syncthreads();
    const uint4* s4 = (const uint4*)sh;
    uint4* d4 = (uint4*)(g_B + (size_t)o*KT);
    for (int k=i; k<KT/8; k+=NI) d4[k] = s4[k];
}

// ---- kernel 3: fp16 mma.sync GEMM: out[4096,256] = A[4096,3072] @ B[256,3072]^T ----
// CTA tile M=64, N=128; 8 warps (2 M x 4 N), warp tile 32x32.
// smem: A buf 2x8KB @ {0,8192}; B buf 2x16KB @ {16384,32768}. Total 48 KB.
__global__ void __launch_bounds__(256) gemm_kernel(float* __restrict__ out){
    extern __shared__ uint8_t smem[];
    const uint32_t sb = smem_u32(smem);
    const int tid = threadIdx.x;
    const int wid = tid>>5, lane = tid&31;
    const int mbase = blockIdx.x*64;
    const int nbase = blockIdx.y*128;
    const int mrow0 = (wid>>2)*32;     // warp M offset within CTA tile
    const int ncol0 = (wid&3)*32;      // warp N offset

    const int lrow = lane&7, sub = lane>>3;
    // ldmatrix lane-address components
    const int a_row = mrow0 + (sub&1)*8 + lrow;  // + mt*16
    const int a_q   = sub>>1;                    // + ks*2
    const int b_rowo = (sub>>1)*8 + lrow;        // + ncol0 + np*16
    const int b_q   = sub&1;                     // + ks*2

    float acc[2][4][4];
    #pragma unroll
    for (int mt=0;mt<2;++mt)
        #pragma unroll
        for (int nt=0;nt<4;++nt)
            #pragma unroll
            for (int r=0;r<4;++r) acc[mt][nt][r]=0.0f;

    // ---- async copy of one K-chunk into buffer ----
    auto issue_copy = [&](int c, int buf){
        const int kb = c*KC;
        #pragma unroll
        for (int it=0; it<6; ++it){
            int idx = tid + it*256;
            const __half* src;
            uint32_t dst;
            if (idx < 512){                 // A tile: 64 rows x 8 chunks of 16B
                int r = idx>>3, q = idx&7;
                src = g_A + (size_t)(mbase+r)*KT + kb + q*8;
                dst = sb + (uint32_t)buf*8192u + SWZ((uint32_t)(r*128 + q*16));
            } else {                        // B tile: 128 rows x 8 chunks
                int j = idx-512; int r = j>>3, q = j&7;
                src = g_B + (size_t)(nbase+r)*KT + kb + q*8;
                dst = sb + 16384u + (uint32_t)buf*16384u + SWZ((uint32_t)(r*128 + q*16));
            }
            asm volatile("cp.async.cg.shared.global [%0], [%1], 16;"
                         :: "r"(dst), "l"(__cvta_generic_to_global(src)));
        }
    };

    issue_copy(0, 0);
    asm volatile("cp.async.commit_group;" ::: "memory");
    issue_copy(1, 1);
    asm volatile("cp.async.commit_group;" ::: "memory");

    for (int i=0; i<NCH; ++i){
        asm volatile("cp.async.wait_group 1;" ::: "memory");
        __syncthreads();
        const uint32_t Ab = sb + (uint32_t)(i&1)*8192u;
        const uint32_t Bb = sb + 16384u + (uint32_t)(i&1)*16384u;
        #pragma unroll
        for (int ks=0; ks<4; ++ks){
            uint32_t a[2][4];
            #pragma unroll
            for (int mt=0; mt<2; ++mt){
                uint32_t addr = Ab + SWZ((uint32_t)((a_row + mt*16)*128 + (ks*2 + a_q)*16));
                asm volatile("ldmatrix.sync.aligned.m8n8.x4.shared.b16 {%0,%1,%2,%3}, [%4];"
                    : "=r"(a[mt][0]),"=r"(a[mt][1]),"=r"(a[mt][2]),"=r"(a[mt][3]) : "r"(addr));
            }
            uint32_t b[2][4];
            #pragma unroll
            for (int np=0; np<2; ++np){
                uint32_t addr = Bb + SWZ((uint32_t)((ncol0 + np*16 + b_rowo)*128 + (ks*2 + b_q)*16));
                asm volatile("ldmatrix.sync.aligned.m8n8.x4.shared.b16 {%0,%1,%2,%3}, [%4];"
                    : "=r"(b[np][0]),"=r"(b[np][1]),"=r"(b[np][2]),"=r"(b[np][3]) : "r"(addr));
            }
            #pragma unroll
            for (int mt=0; mt<2; ++mt)
                #pragma unroll
                for (int nt=0; nt<4; ++nt){
                    uint32_t b0 = b[nt>>1][(nt&1)*2], b1 = b[nt>>1][(nt&1)*2+1];
                    asm volatile(
                        "mma.sync.aligned.m16n8k16.row.col.f32.f16.f16.f32 "
                        "{%0,%1,%2,%3}, {%4,%5,%6,%7}, {%8,%9}, {%0,%1,%2,%3};"
                        : "+f"(acc[mt][nt][0]),"+f"(acc[mt][nt][1]),
                          "+f"(acc[mt][nt][2]),"+f"(acc[mt][nt][3])
                        : "r"(a[mt][0]),"r"(a[mt][1]),"r"(a[mt][2]),"r"(a[mt][3]),
                          "r"(b0),"r"(b1));
                }
        }
        __syncthreads();
        if (i+2 < NCH) issue_copy(i+2, i&1);
        asm volatile("cp.async.commit_group;" ::: "memory");
    }

    // epilogue: direct fp32 store
    const int g = lane>>2, tt = lane&3;
    #pragma unroll
    for (int mt=0; mt<2; ++mt){
        #pragma unroll
        for (int nt=0; nt<4; ++nt){
            int row = mbase + mrow0 + mt*16 + g;
            int col = nbase + ncol0 + nt*8 + tt*2;
            float2 v0 = make_float2(acc[mt][nt][0], acc[mt][nt][1]);
            float2 v1 = make_float2(acc[mt][nt][2], acc[mt][nt][3]);
            *(float2*)(out + (size_t)row*NO + col)     = v0;
            *(float2*)(out + (size_t)(row+8)*NO + col) = v1;
        }
    }
}

extern "C" void kernel_launch(void* const* d_in, const int* in_sizes, int n_in,
                              void* d_out, int out_size){
    const float *x=nullptr, *cp=nullptr, *sf=nullptr;
    for (int i=0; i<n_in; ++i){
        if      (in_sizes[i] == NB*NI)    x  = (const float*)d_in[i];
        else if (in_sizes[i] == NI*NO*19) cp = (const float*)d_in[i];
        else if (in_sizes[i] == NI*NO)    sf = (const float*)d_in[i];
    }
    feat_kernel<<<NB, NI>>>(x);
    prep_kernel<<<NO, NI>>>(cp, sf);
    gemm_kernel<<<dim3(NB/64, NO/128), 256, 49152>>>((float*)d_out);
}